// round 13
// baseline (speedup 1.0000x reference)
#include <cuda_runtime.h>

// HashEmbedder: 16-level multires hash grid, F=2, IN_DIM=3, K=8 corners.
// Levels 0..5 dense (row-major), 6..15 hashed (XOR-prime, mod 524309).
// ILP=4: each thread processes ONE level for FOUR points (p + t*npts/4).
// Same level => same dense/hash branch for all items (no extra divergence);
// 32 independent gathers front-batched per thread (MLP 16 -> 32). ILP=2
// measured faster than ILP=1 despite halved occupancy: the L1tex miss pipe
// is fed by per-thread MLP, not warp count.

#define T_HASH 524309ULL
// Barrett magic: floor(2^64/T)+1. Exact for n < 2^38 (error term < 2^-45).
#define BARRETT_M ((0xFFFFFFFFFFFFFFFFULL / T_HASH) + 1ULL)

#define ILP 4

__device__ __forceinline__ unsigned int mod_T(unsigned long long n) {
    unsigned long long q = __umul64hi(n, BARRETT_M);
    return (unsigned int)(n - q * T_HASH);
}

// Per-level resolutions: int(16 * 1.38^i). All >0.04 from integer boundaries.
__device__ const int g_n[16] = {16,22,30,42,58,80,110,152,210,290,400,553,763,1053,1453,2005};
// ENTRIES_SIZE = float32(1.0/(n-1)) — same double->float rounding as numpy.
__device__ const float g_es[16] = {
    (float)(1.0/15.0),   (float)(1.0/21.0),   (float)(1.0/29.0),   (float)(1.0/41.0),
    (float)(1.0/57.0),   (float)(1.0/79.0),   (float)(1.0/109.0),  (float)(1.0/151.0),
    (float)(1.0/209.0),  (float)(1.0/289.0),  (float)(1.0/399.0),  (float)(1.0/552.0),
    (float)(1.0/762.0),  (float)(1.0/1052.0), (float)(1.0/1452.0), (float)(1.0/2004.0)};
// cumsum of n^3 for dense levels
__device__ const int g_base[6] = {0, 4096, 14744, 41744, 115832, 310944};

__global__ void __launch_bounds__(256)
hashenc_kernel(const float* __restrict__ xyz,
               const float* __restrict__ dense,
               const float* __restrict__ hasht,
               float* __restrict__ out,
               int npts)
{
    int idx = blockIdx.x * 256 + threadIdx.x;
    int quarter = npts >> 2;               // npts = 131072, divisible by 4
    int p0 = idx >> 4;                     // first point
    if (p0 >= quarter) return;
    int l = idx & 15;                      // level (same for all items)

    int   n   = g_n[l];
    int   nm1 = n - 1;
    float es  = g_es[l];

    // Per-item state
    int   A0[ILP], B0[ILP], A1[ILP], B1[ILP], A2[ILP], B2[ILP];
    float w00[ILP], w01[ILP], w10[ILP], w11[ILP];
    float2 v[ILP][8];

    #pragma unroll
    for (int t = 0; t < ILP; t++) {
        int p = p0 + t * quarter;
        float x0 = xyz[3 * p + 0];
        float x1 = xyz[3 * p + 1];
        float x2 = xyz[3 * p + 2];

        if (l == 0) {    // include_input passthrough (bounds [0,1] -> identity)
            float* orow = out + (long long)p * 35;
            orow[0] = x0; orow[1] = x1; orow[2] = x2;
        }

        // flt = x / entries_size (IEEE f32 divide, matching reference exactly)
        float f0 = __fdiv_rn(x0, es);
        float f1 = __fdiv_rn(x1, es);
        float f2 = __fdiv_rn(x2, es);

        // trunc == floor (flt >= 0); flt+1 exact below 2^23.
        int i0 = (int)f0, i1 = (int)f1, i2 = (int)f2;
        int a0 = min(i0, nm1),     a1 = min(i1, nm1),     a2 = min(i2, nm1);
        int b0 = min(i0 + 1, nm1), b1 = min(i1 + 1, nm1), b2 = min(i2 + 1, nm1);

        float o0 = f0 - (float)a0;
        float o1 = f1 - (float)a1;
        float u0 = 1.0f - o0, u1 = 1.0f - o1;
        w00[t] = u0 * u1; w01[t] = u0 * o1; w10[t] = o0 * u1; w11[t] = o0 * o1;

        A0[t] = a0; B0[t] = b0; A1[t] = a1; B1[t] = b1; A2[t] = a2; B2[t] = b2;
    }

    if (l < 6) {
        const float2* d2 = (const float2*)dense;
        int base = g_base[l];
        int s1 = n, s0 = n * n;
        #pragma unroll
        for (int t = 0; t < ILP; t++) {
            int a0s = A0[t] * s0 + base, b0s = B0[t] * s0 + base;
            int a1s = A1[t] * s1,        b1s = B1[t] * s1;
            v[t][0] = __ldg(d2 + (a0s + a1s + A2[t]));
            v[t][1] = __ldg(d2 + (a0s + a1s + B2[t]));
            v[t][2] = __ldg(d2 + (a0s + b1s + A2[t]));
            v[t][3] = __ldg(d2 + (a0s + b1s + B2[t]));
            v[t][4] = __ldg(d2 + (b0s + a1s + A2[t]));
            v[t][5] = __ldg(d2 + (b0s + a1s + B2[t]));
            v[t][6] = __ldg(d2 + (b0s + b1s + A2[t]));
            v[t][7] = __ldg(d2 + (b0s + b1s + B2[t]));
        }
    } else {
        const float2* h2 = (const float2*)hasht + (unsigned long long)(l - 6) * T_HASH;
        #pragma unroll
        for (int t = 0; t < ILP; t++) {
            // ih = 1 ^ (x0*1) ^ (x1*19349663) ^ (x2*83492791), then % T
            unsigned long long A0h = 1ULL ^ (unsigned long long)(unsigned)A0[t];
            unsigned long long B0h = 1ULL ^ (unsigned long long)(unsigned)B0[t];
            unsigned long long A1h = (unsigned long long)(unsigned)A1[t] * 19349663ULL;
            unsigned long long B1h = (unsigned long long)(unsigned)B1[t] * 19349663ULL;
            unsigned long long A2h = (unsigned long long)(unsigned)A2[t] * 83492791ULL;
            unsigned long long B2h = (unsigned long long)(unsigned)B2[t] * 83492791ULL;
            v[t][0] = __ldg(h2 + mod_T(A0h ^ A1h ^ A2h));
            v[t][1] = __ldg(h2 + mod_T(A0h ^ A1h ^ B2h));
            v[t][2] = __ldg(h2 + mod_T(A0h ^ B1h ^ A2h));
            v[t][3] = __ldg(h2 + mod_T(A0h ^ B1h ^ B2h));
            v[t][4] = __ldg(h2 + mod_T(B0h ^ A1h ^ A2h));
            v[t][5] = __ldg(h2 + mod_T(B0h ^ A1h ^ B2h));
            v[t][6] = __ldg(h2 + mod_T(B0h ^ B1h ^ A2h));
            v[t][7] = __ldg(h2 + mod_T(B0h ^ B1h ^ B2h));
        }
    }

    #pragma unroll
    for (int t = 0; t < ILP; t++) {
        float rx = w00[t] * (v[t][0].x + v[t][1].x) + w01[t] * (v[t][2].x + v[t][3].x)
                 + w10[t] * (v[t][4].x + v[t][5].x) + w11[t] * (v[t][6].x + v[t][7].x);
        float ry = w00[t] * (v[t][0].y + v[t][1].y) + w01[t] * (v[t][2].y + v[t][3].y)
                 + w10[t] * (v[t][4].y + v[t][5].y) + w11[t] * (v[t][6].y + v[t][7].y);
        float* orow = out + (long long)(p0 + t * quarter) * 35;
        orow[3 + 2 * l] = rx;   // row stride 35 floats (odd) -> keep scalar stores
        orow[4 + 2 * l] = ry;
    }
}

extern "C" void kernel_launch(void* const* d_in, const int* in_sizes, int n_in,
                              void* d_out, int out_size) {
    const float* xyz   = (const float*)d_in[0];   // (2,65536,3) f32
    const float* dense = (const float*)d_in[1];   // (822944,2) f32
    const float* hasht = (const float*)d_in[2];   // (10,524309,2) f32
    float* out = (float*)d_out;                   // (2,65536,35) f32

    int npts = in_sizes[0] / 3;
    int total = (npts / ILP) * 16;                // npts divisible by 4 (131072)
    int blocks = (total + 255) / 256;
    hashenc_kernel<<<blocks, 256>>>(xyz, dense, hasht, out, npts);
}

// round 14
// speedup vs baseline: 1.1298x; 1.1298x over previous
#include <cuda_runtime.h>

// HashEmbedder: 16-level multires hash grid, F=2, IN_DIM=3, K=8 corners.
// Levels 0..5 dense (row-major), 6..15 hashed (XOR-prime, mod 524309).
// Level-paired ILP=2: each thread processes levels (l, l+8) of ONE point
// (8 threads/point). Same MLP=16 as the best point-paired ILP2 kernel, but
// xyz loads / point math / row address are computed once per thread.
// Dense corner-pairs along dim2 are loaded as float4 when sector-aligned
// (weights ignore dim2; pair is summed anyway).

#define T_HASH 524309ULL
// Barrett magic: floor(2^64/T)+1. Exact for n < 2^38 (error term < 2^-45).
#define BARRETT_M ((0xFFFFFFFFFFFFFFFFULL / T_HASH) + 1ULL)

__device__ __forceinline__ unsigned int mod_T(unsigned long long n) {
    unsigned long long q = __umul64hi(n, BARRETT_M);
    return (unsigned int)(n - q * T_HASH);
}

// Per-level resolutions: int(16 * 1.38^i). All >0.04 from integer boundaries.
__device__ const int g_n[16] = {16,22,30,42,58,80,110,152,210,290,400,553,763,1053,1453,2005};
// ENTRIES_SIZE = float32(1.0/(n-1)) — same double->float rounding as numpy.
__device__ const float g_es[16] = {
    (float)(1.0/15.0),   (float)(1.0/21.0),   (float)(1.0/29.0),   (float)(1.0/41.0),
    (float)(1.0/57.0),   (float)(1.0/79.0),   (float)(1.0/109.0),  (float)(1.0/151.0),
    (float)(1.0/209.0),  (float)(1.0/289.0),  (float)(1.0/399.0),  (float)(1.0/552.0),
    (float)(1.0/762.0),  (float)(1.0/1052.0), (float)(1.0/1452.0), (float)(1.0/2004.0)};
// cumsum of n^3 for dense levels
__device__ const int g_base[6] = {0, 4096, 14744, 41744, 115832, 310944};

struct Corners {
    int a0, b0, a1, b1, a2, b2;
    float w00, w01, w10, w11;
};

// Index/weight computation for one level. IEEE-exact vs reference:
// __fdiv_rn divide, trunc==floor (x>=0), +1 exact below 2^23.
__device__ __forceinline__ Corners setup(float x0, float x1, float x2, int l) {
    Corners c;
    float es = g_es[l];
    int nm1 = g_n[l] - 1;
    float f0 = __fdiv_rn(x0, es);
    float f1 = __fdiv_rn(x1, es);
    float f2 = __fdiv_rn(x2, es);
    int i0 = (int)f0, i1 = (int)f1, i2 = (int)f2;
    c.a0 = min(i0, nm1);     c.a1 = min(i1, nm1);     c.a2 = min(i2, nm1);
    c.b0 = min(i0 + 1, nm1); c.b1 = min(i1 + 1, nm1); c.b2 = min(i2 + 1, nm1);
    float o0 = f0 - (float)c.a0;
    float o1 = f1 - (float)c.a1;
    float u0 = 1.0f - o0, u1 = 1.0f - o1;   // weights use dims 0,1 only (as in source)
    c.w00 = u0 * u1; c.w01 = u0 * o1; c.w10 = o0 * u1; c.w11 = o0 * o1;
    return c;
}

// Sum of dense corners j=ja, j=jb (jb==ja+1 or ja when clipped), table as
// float4: 16B loads never split a 32B sector; even ja -> one load for both.
__device__ __forceinline__ float2 dense_pair_sum(const float4* __restrict__ d4,
                                                 int ja, int jb) {
    int ka = ja >> 1, kb = jb >> 1;
    float4 qa = __ldg(d4 + ka);
    float4 qb = qa;
    if (kb != ka) qb = __ldg(d4 + kb);   // small body -> predicated @P LDG
    float lox = (ja & 1) ? qa.z : qa.x;
    float loy = (ja & 1) ? qa.w : qa.y;
    float hix = (jb & 1) ? qb.z : qb.x;
    float hiy = (jb & 1) ? qb.w : qb.y;
    return make_float2(lox + hix, loy + hiy);
}

// 8 hash-table gathers for one level; ih = 1 ^ a0 ^ a1*P1 ^ a2*P2 (64-bit), % T.
__device__ __forceinline__ void hash_loads(const float2* __restrict__ h2,
                                           const Corners& c, float2 v[8]) {
    unsigned long long A0h = 1ULL ^ (unsigned long long)(unsigned)c.a0;
    unsigned long long B0h = 1ULL ^ (unsigned long long)(unsigned)c.b0;
    unsigned long long A1h = (unsigned long long)(unsigned)c.a1 * 19349663ULL;
    unsigned long long B1h = (unsigned long long)(unsigned)c.b1 * 19349663ULL;
    unsigned long long A2h = (unsigned long long)(unsigned)c.a2 * 83492791ULL;
    unsigned long long B2h = (unsigned long long)(unsigned)c.b2 * 83492791ULL;
    v[0] = __ldg(h2 + mod_T(A0h ^ A1h ^ A2h));
    v[1] = __ldg(h2 + mod_T(A0h ^ A1h ^ B2h));
    v[2] = __ldg(h2 + mod_T(A0h ^ B1h ^ A2h));
    v[3] = __ldg(h2 + mod_T(A0h ^ B1h ^ B2h));
    v[4] = __ldg(h2 + mod_T(B0h ^ A1h ^ A2h));
    v[5] = __ldg(h2 + mod_T(B0h ^ A1h ^ B2h));
    v[6] = __ldg(h2 + mod_T(B0h ^ B1h ^ A2h));
    v[7] = __ldg(h2 + mod_T(B0h ^ B1h ^ B2h));
}

__global__ void __launch_bounds__(256)
hashenc_kernel(const float* __restrict__ xyz,
               const float* __restrict__ dense,
               const float* __restrict__ hasht,
               float* __restrict__ out,
               int npts)
{
    int idx = blockIdx.x * 256 + threadIdx.x;
    int p = idx >> 3;            // point (8 threads per point)
    if (p >= npts) return;
    int l = idx & 7;             // item0 level 0..7; item1 level = l+8

    float x0 = xyz[3 * p + 0];
    float x1 = xyz[3 * p + 1];
    float x2 = xyz[3 * p + 2];

    float* orow = out + (long long)p * 35;
    if (l == 0) {                // include_input passthrough (bounds [0,1])
        orow[0] = x0; orow[1] = x1; orow[2] = x2;
    }

    Corners c0 = setup(x0, x1, x2, l);       // levels 0..7 (0..5 dense, 6..7 hash)
    Corners c1 = setup(x0, x1, x2, l + 8);   // levels 8..15 (always hash)

    // Item0 gathers: dense (float4 pair-merged sums) or hash.
    float2 s00, s01, s10, s11;               // item0 per-(d0,d1) pair sums
    float2 v1a[8];                            // item1 raw corners
    if (l < 6) {
        const float4* d4 = (const float4*)dense;
        int n = g_n[l];
        int s1 = n, s0 = n * n;
        int base = g_base[l];
        int A0 = c0.a0 * s0 + base, B0 = c0.b0 * s0 + base;
        int A1 = c0.a1 * s1,        B1 = c0.b1 * s1;
        s00 = dense_pair_sum(d4, A0 + A1 + c0.a2, A0 + A1 + c0.b2);
        s01 = dense_pair_sum(d4, A0 + B1 + c0.a2, A0 + B1 + c0.b2);
        s10 = dense_pair_sum(d4, B0 + A1 + c0.a2, B0 + A1 + c0.b2);
        s11 = dense_pair_sum(d4, B0 + B1 + c0.a2, B0 + B1 + c0.b2);
    } else {
        const float2* h2 = (const float2*)hasht + (unsigned long long)(l - 6) * T_HASH;
        float2 v[8];
        hash_loads(h2, c0, v);
        s00 = make_float2(v[0].x + v[1].x, v[0].y + v[1].y);
        s01 = make_float2(v[2].x + v[3].x, v[2].y + v[3].y);
        s10 = make_float2(v[4].x + v[5].x, v[4].y + v[5].y);
        s11 = make_float2(v[6].x + v[7].x, v[6].y + v[7].y);
    }
    {
        const float2* h2 = (const float2*)hasht + (unsigned long long)(l + 2) * T_HASH; // (l+8)-6
        hash_loads(h2, c1, v1a);
    }

    // Item0 reduce + store
    {
        float rx = c0.w00 * s00.x + c0.w01 * s01.x + c0.w10 * s10.x + c0.w11 * s11.x;
        float ry = c0.w00 * s00.y + c0.w01 * s01.y + c0.w10 * s10.y + c0.w11 * s11.y;
        orow[3 + 2 * l] = rx;
        orow[4 + 2 * l] = ry;
    }
    // Item1 reduce + store
    {
        float rx = c1.w00 * (v1a[0].x + v1a[1].x) + c1.w01 * (v1a[2].x + v1a[3].x)
                 + c1.w10 * (v1a[4].x + v1a[5].x) + c1.w11 * (v1a[6].x + v1a[7].x);
        float ry = c1.w00 * (v1a[0].y + v1a[1].y) + c1.w01 * (v1a[2].y + v1a[3].y)
                 + c1.w10 * (v1a[4].y + v1a[5].y) + c1.w11 * (v1a[6].y + v1a[7].y);
        orow[19 + 2 * l] = rx;   // 3 + 2*(l+8)
        orow[20 + 2 * l] = ry;
    }
}

extern "C" void kernel_launch(void* const* d_in, const int* in_sizes, int n_in,
                              void* d_out, int out_size) {
    const float* xyz   = (const float*)d_in[0];   // (2,65536,3) f32
    const float* dense = (const float*)d_in[1];   // (822944,2) f32
    const float* hasht = (const float*)d_in[2];   // (10,524309,2) f32
    float* out = (float*)d_out;                   // (2,65536,35) f32

    int npts = in_sizes[0] / 3;
    int total = npts * 8;
    int blocks = (total + 255) / 256;
    hashenc_kernel<<<blocks, 256>>>(xyz, dense, hasht, out, npts);
}